// round 13
// baseline (speedup 1.0000x reference)
#include <cuda_runtime.h>
#include <cuda_fp16.h>

typedef unsigned int u32;

#define NB 4
#define NT 8192
#define NC 128
#define NL 40

// ---------------- persistent device scratch ----------------
__device__ float g_hA[NB * NT * NC];
__device__ float g_hB[NB * NT * NC];
__device__ __align__(128) __half g_h16A[NB * NT * NC];  // fp16 shadow of h (ping)
__device__ __align__(128) __half g_h16B[NB * NT * NC];  // fp16 shadow of h (pong)
__device__ float g_skip[NB * NT * NC];
// XOR-swizzled smem-image layouts (fp16, unpadded):
// conv: per layer 8 chunks x [256 o'][32 k] ; row 64B, swz = ((o'>>1)&3)<<4
__device__ __align__(128) char g_wconv2[(size_t)NL * 131072];
// post: per layer 2 chunks x [128 o][64 k] ; row 128B, swz = (o&7)<<4
__device__ __align__(128) char g_wpost2[(size_t)NL * 32768];
// lin (final kernel, padded-72 layout as before)
__device__ __align__(128) __half g_lin_h[2 * 2 * 128 * 72];

// ---------------- helpers ----------------
__device__ __forceinline__ u32 smem_u32(const void* p) {
    u32 a;
    asm("{ .reg .u64 t; cvta.to.shared.u64 t, %1; cvt.u32.u64 %0, t; }" : "=r"(a) : "l"(p));
    return a;
}
__device__ __forceinline__ void cpa16(u32 dst, const void* src) {
    asm volatile("cp.async.cg.shared.global [%0], [%1], 16;" :: "r"(dst), "l"(src));
}
__device__ __forceinline__ void cpa16z(u32 dst, const void* src, u32 n) {
    asm volatile("cp.async.cg.shared.global [%0], [%1], 16, %2;" :: "r"(dst), "l"(src), "r"(n));
}
#define CP_COMMIT() asm volatile("cp.async.commit_group;" ::: "memory")
#define CP_WAIT0() asm volatile("cp.async.wait_group 0;" ::: "memory")
#define CP_WAIT1() asm volatile("cp.async.wait_group 1;" ::: "memory")

__device__ __forceinline__ void mma16(float c[4], const u32 a[4], u32 b0, u32 b1) {
    asm volatile(
        "mma.sync.aligned.m16n8k16.row.col.f32.f16.f16.f32 "
        "{%0,%1,%2,%3}, {%4,%5,%6,%7}, {%8,%9}, {%0,%1,%2,%3};"
        : "+f"(c[0]), "+f"(c[1]), "+f"(c[2]), "+f"(c[3])
        : "r"(a[0]), "r"(a[1]), "r"(a[2]), "r"(a[3]), "r"(b0), "r"(b1));
}

// ---------------- weight transposes (fp16, swizzled images) -----------------

__global__ void tconv_kernel(const float* __restrict__ w) {
    // w: [L][256 og][128 c][2 tap]
    int idx = blockIdx.x * blockDim.x + threadIdx.x;  // NL*256*128*2
    int tap = idx & 1;
    int c = (idx >> 1) & 127;
    int og = (idx >> 8) & 255;
    int l = idx >> 16;
    int kg = tap * 128 + c;               // K: 0-127 = h[t-d], 128-255 = h[t]
    int kc = kg >> 5, ki = kg & 31;
    int op = (og < 128) ? (og * 2) : ((og - 128) * 2 + 1);  // interleave filter/gate
    u32 off = (u32)kc * 16384 + (u32)op * 64 + (((u32)ki * 2) ^ ((((u32)op >> 1) & 3) << 4));
    *(__half*)(g_wconv2 + (size_t)l * 131072 + off) = __float2half_rn(w[idx]);
}

__global__ void tpost_kernel(const float* __restrict__ w) {
    // w: [L][128 o][128 c]
    int idx = blockIdx.x * blockDim.x + threadIdx.x;  // NL*128*128
    int c = idx & 127;
    int o = (idx >> 7) & 127;
    int l = idx >> 14;
    int pc = c >> 6, ki = c & 63;
    u32 off = (u32)pc * 16384 + (u32)o * 128 + (((u32)ki * 2) ^ (((u32)o & 7) << 4));
    *(__half*)(g_wpost2 + (size_t)l * 32768 + off) = __float2half_rn(w[idx]);
}

__global__ void tlin_kernel(const float* __restrict__ w, int which) {
    // w: [128 o][128 i]  (padded-72 layout for final_kernel)
    int idx = blockIdx.x * blockDim.x + threadIdx.x;  // 128*128
    int i = idx & 127;
    int o = idx >> 7;
    g_lin_h[((which * 2 + (i >> 6)) * 128 + o) * 72 + (i & 63)] = __float2half_rn(w[idx]);
}

// ---------------- pre-net ----------------

__global__ void pre_kernel(const float* __restrict__ x,
                           const float* __restrict__ w,
                           const float* __restrict__ b) {
    int bt = blockIdx.x;
    int bb = bt >> 13;
    int t = bt & 8191;
    int c = threadIdx.x;
    const float* xb = x + bb * NT;
    float x0 = (t >= 2) ? xb[t - 2] : 0.f;
    float x1 = (t >= 1) ? xb[t - 1] : 0.f;
    float x2 = xb[t];
    float v = w[c * 3 + 0] * x0 + w[c * 3 + 1] * x1 + w[c * 3 + 2] * x2 + b[c];
    g_hA[bt * NC + c] = v;
    g_h16A[bt * NC + c] = __float2half_rn(v);
}

// ---------------- fused WaveNet block: weights resident, batch loop ---------
// smem bytes: X 2 bufs x [64 rows][512B swz] = 65536 @0;
//             conv W 8x16384 = 131072 @65536; post W 2x16384 = 32768 @196608.
// grid = 128 (one CTA per t-tile), each CTA loops b = 0..3.

#define SMEM_LAYER 229376

__global__ void __launch_bounds__(256, 1)
layer_kernel(int l, int dil, int flip, int first,
             const float* __restrict__ conv_b,
             const float* __restrict__ post_b) {
    const float* __restrict__ h_in = flip ? g_hB : g_hA;
    float* __restrict__ h_out = flip ? g_hA : g_hB;
    const __half* __restrict__ h16_in = flip ? g_h16B : g_h16A;
    __half* __restrict__ h16_out = flip ? g_h16A : g_h16B;

    extern __shared__ char smx[];
    u32 smb = smem_u32(smx);

    int tid = threadIdx.x;
    int lane = tid & 31, wid = tid >> 5;
    int g = lane >> 2, tig = lane & 3;
    int m_idx = wid >> 2, n_idx = wid & 3;
    u32 xg = (u32)g << 4;                 // X / post-W swizzle (row ≡ g mod 8)
    u32 xb2 = (((u32)g >> 1) & 3) << 4;   // conv-W swizzle ((o'>>1)&3 ≡ (g>>1)&3)

    int t0 = blockIdx.x << 6;

    const char* wcl = g_wconv2 + (size_t)l * 131072;
    const char* wpl = g_wpost2 + (size_t)l * 32768;

    // G0: X tile for b=0
    {
        const __half* h16b = h16_in;
#pragma unroll
        for (int j = 0; j < 8; j++) {
            int e = tid + j * 256;
            int row = e >> 5, s = e & 31;
            u32 dst = smb + row * 512 + (((u32)s * 16) ^ (((u32)row & 7) << 4));
            if (s < 16) {
                int tp = t0 + row - dil;
                cpa16z(dst, h16b + (size_t)(tp < 0 ? 0 : tp) * NC + s * 8, (tp >= 0) ? 16u : 0u);
            } else {
                cpa16(dst, h16b + (size_t)(t0 + row) * NC + (s - 16) * 8);
            }
        }
        CP_COMMIT();
    }
    // G1: conv weights (128KB, flat — already swizzled in global)
#pragma unroll
    for (int j = 0; j < 32; j++)
        cpa16(smb + 65536 + (tid + j * 256) * 16, wcl + (tid + j * 256) * 16);
    CP_COMMIT();
    // G2: post weights (32KB)
#pragma unroll
    for (int j = 0; j < 8; j++)
        cpa16(smb + 196608 + (tid + j * 256) * 16, wpl + (tid + j * 256) * 16);
    CP_COMMIT();

    int r0 = m_idx * 32 + g;

#pragma unroll 1
    for (int i = 0; i < 4; i++) {
        char* Xb = smx + (i & 1) * 32768;
        if (i == 0) CP_WAIT1(); else CP_WAIT0();  // X_i (+conv W at i=0) arrived
        __syncthreads();
        if (i < 3) {
            // prefetch X for b=i+1 into the other buffer
            const __half* h16b = h16_in + (size_t)(i + 1) * NT * NC;
            u32 dbase = smb + ((i + 1) & 1) * 32768;
#pragma unroll
            for (int j = 0; j < 8; j++) {
                int e = tid + j * 256;
                int row = e >> 5, s = e & 31;
                u32 dst = dbase + row * 512 + (((u32)s * 16) ^ (((u32)row & 7) << 4));
                if (s < 16) {
                    int tp = t0 + row - dil;
                    cpa16z(dst, h16b + (size_t)(tp < 0 ? 0 : tp) * NC + s * 8, (tp >= 0) ? 16u : 0u);
                } else {
                    cpa16(dst, h16b + (size_t)(t0 + row) * NC + (s - 16) * 8);
                }
            }
            CP_COMMIT();
        }

        // ---- conv GEMM: C[64t,256o'] = X[64,256] * W[256,256], barrier-free
        float acc[2][8][4];
#pragma unroll
        for (int mt = 0; mt < 2; mt++)
#pragma unroll
            for (int nt = 0; nt < 8; nt++)
#pragma unroll
                for (int q = 0; q < 4; q++) acc[mt][nt][q] = 0.f;

#pragma unroll 1
        for (int kc = 0; kc < 8; kc++) {
            const char* Wc = smx + 65536 + kc * 16384;
#pragma unroll
            for (int ks = 0; ks < 2; ks++) {
                int kb = ks * 32 + tig * 4;
                int ko = kc * 64 + kb;
                u32 A[2][4];
#pragma unroll
                for (int mt = 0; mt < 2; mt++) {
                    int r = r0 + mt * 16;
                    A[mt][0] = *(const u32*)(Xb + r * 512 + (ko ^ xg));
                    A[mt][1] = *(const u32*)(Xb + (r + 8) * 512 + (ko ^ xg));
                    A[mt][2] = *(const u32*)(Xb + r * 512 + ((ko + 16) ^ xg));
                    A[mt][3] = *(const u32*)(Xb + (r + 8) * 512 + ((ko + 16) ^ xg));
                }
#pragma unroll
                for (int nt = 0; nt < 8; nt++) {
                    int n = n_idx * 64 + nt * 8 + g;
                    u32 B0 = *(const u32*)(Wc + n * 64 + (kb ^ xb2));
                    u32 B1 = *(const u32*)(Wc + n * 64 + ((kb + 16) ^ xb2));
                    mma16(acc[0][nt], A[0], B0, B1);
                    mma16(acc[1][nt], A[1], B0, B1);
                }
            }
        }
        __syncthreads();  // conv X-reads done before skip overwrites X cols 0-127

        // ---- GLU: skip = a*sigmoid(gate); skip_sum RMW; skip -> Xb bytes 0-255
        const float* cbl = conv_b + l * 256;
        float* gsk = g_skip + ((size_t)i * NT + t0) * NC;
#pragma unroll
        for (int nt = 0; nt < 8; nt++) {
            int o0 = n_idx * 64 + nt * 8 + tig * 2;
            int ch = o0 >> 1;
            float cb0 = __ldg(cbl + ch);
            float cb1 = __ldg(cbl + 128 + ch);
#pragma unroll
            for (int mt = 0; mt < 2; mt++) {
                int rr = r0 + mt * 16;
                float a0 = acc[mt][nt][0] + cb0, g0 = acc[mt][nt][1] + cb1;
                float a1 = acc[mt][nt][2] + cb0, g1 = acc[mt][nt][3] + cb1;
                float s0 = a0 / (1.f + __expf(-g0));
                float s1 = a1 / (1.f + __expf(-g1));
                if (first) {
                    gsk[rr * NC + ch] = s0;
                    gsk[(rr + 8) * NC + ch] = s1;
                } else {
                    gsk[rr * NC + ch] += s0;
                    gsk[(rr + 8) * NC + ch] += s1;
                }
                *(__half*)(Xb + rr * 512 + (((u32)ch * 2) ^ xg)) = __float2half_rn(s0);
                *(__half*)(Xb + (rr + 8) * 512 + (((u32)ch * 2) ^ xg)) = __float2half_rn(s1);
            }
        }
        if (i == 0) CP_WAIT1();  // post W arrived (X1 prefetch may stay pending)
        __syncthreads();         // skip stores visible

        // ---- post GEMM: D[64t,128o] = skip[64,128] * Wp[128,128]
        float accp[2][4][4];
#pragma unroll
        for (int mt = 0; mt < 2; mt++)
#pragma unroll
            for (int nt = 0; nt < 4; nt++)
#pragma unroll
                for (int q = 0; q < 4; q++) accp[mt][nt][q] = 0.f;

#pragma unroll
        for (int pc = 0; pc < 2; pc++) {
            const char* Wp = smx + 196608 + pc * 16384;
#pragma unroll
            for (int ks = 0; ks < 4; ks++) {
                int kb = ks * 32 + tig * 4;
                int ko = pc * 128 + kb;
                u32 A[2][4];
#pragma unroll
                for (int mt = 0; mt < 2; mt++) {
                    int r = r0 + mt * 16;
                    A[mt][0] = *(const u32*)(Xb + r * 512 + (ko ^ xg));
                    A[mt][1] = *(const u32*)(Xb + (r + 8) * 512 + (ko ^ xg));
                    A[mt][2] = *(const u32*)(Xb + r * 512 + ((ko + 16) ^ xg));
                    A[mt][3] = *(const u32*)(Xb + (r + 8) * 512 + ((ko + 16) ^ xg));
                }
#pragma unroll
                for (int nt = 0; nt < 4; nt++) {
                    int n = n_idx * 32 + nt * 8 + g;
                    u32 B0 = *(const u32*)(Wp + n * 128 + (kb ^ xg));
                    u32 B1 = *(const u32*)(Wp + n * 128 + ((kb + 16) ^ xg));
                    mma16(accp[0][nt], A[0], B0, B1);
                    mma16(accp[1][nt], A[1], B0, B1);
                }
            }
        }

        // ---- residual epilogue (fp32 h path) + fp16 shadow ----
        const float* hres = h_in + ((size_t)i * NT + t0) * NC;
        float* hdst = h_out + ((size_t)i * NT + t0) * NC;
        __half* hdst16 = h16_out + ((size_t)i * NT + t0) * NC;
        const float* pbl = post_b + l * 128;
#pragma unroll
        for (int nt = 0; nt < 4; nt++) {
            int o0 = n_idx * 32 + nt * 8 + tig * 2;
            float pb0 = __ldg(pbl + o0), pb1 = __ldg(pbl + o0 + 1);
#pragma unroll
            for (int mt = 0; mt < 2; mt++) {
                int rr = r0 + mt * 16;
                float2 h0 = *(const float2*)(hres + rr * NC + o0);
                float2 h1 = *(const float2*)(hres + (rr + 8) * NC + o0);
                float2 v0, v1;
                v0.x = h0.x + accp[mt][nt][0] + pb0;
                v0.y = h0.y + accp[mt][nt][1] + pb1;
                v1.x = h1.x + accp[mt][nt][2] + pb0;
                v1.y = h1.y + accp[mt][nt][3] + pb1;
                *(float2*)(hdst + rr * NC + o0) = v0;
                *(float2*)(hdst + (rr + 8) * NC + o0) = v1;
                *(__half2*)(hdst16 + rr * NC + o0) = __floats2half2_rn(v0.x, v0.y);
                *(__half2*)(hdst16 + (rr + 8) * NC + o0) = __floats2half2_rn(v1.x, v1.y);
            }
        }
        // next iteration's head CP_WAIT + barrier orders buffer reuse
    }
}

// ---------------- final: relu -> lin1 -> relu -> lin2 (fp16 mma) ------------
// unchanged from R10 (passed): Z [64][136]h @0; WB @17408 (2x9216h); biases.

#define FWB_B 17408
#define FB1_B 54272
#define FB2_B 54784
#define SMEM_FINAL 55296
#define ZS 136

__global__ void __launch_bounds__(256, 2)
final_kernel(const float* __restrict__ lin1_b,
             const float* __restrict__ lin2_b,
             float* __restrict__ out) {
    extern __shared__ char smx[];
    __half* Z = (__half*)smx;
    __half* WB = (__half*)(smx + FWB_B);
    float* B1S = (float*)(smx + FB1_B);
    float* B2S = (float*)(smx + FB2_B);
    u32 smb = smem_u32(smx);

    int tid = threadIdx.x;
    int lane = tid & 31, wid = tid >> 5;
    int g = lane >> 2, tig = lane & 3;
    int m_idx = wid >> 2, n_idx = wid & 3;

    int b = blockIdx.x >> 7;
    int t0 = (blockIdx.x & 127) << 6;

#pragma unroll
    for (int pc = 0; pc < 2; pc++) {
        u32 d = smb + FWB_B + pc * 18432;
        const char* s = (const char*)(g_lin_h) + pc * 18432;
#pragma unroll
        for (int j = 0; j < 5; j++) {
            int e = tid + j * 256;
            if (e < 1152) cpa16(d + e * 16, s + e * 16);
        }
        CP_COMMIT();
    }

    if (tid < 128) {
        B1S[tid] = lin1_b[tid];
        B2S[tid] = lin2_b[tid];
    }

    const float* zb = g_skip + ((size_t)b * NT + t0) * NC;
#pragma unroll
    for (int i = 0; i < 8; i++) {
        int e = tid + i * 256;
        int row = e >> 5, q = e & 31;
        float4 v = *(const float4*)(zb + (size_t)row * NC + q * 4);
        v.x = fmaxf(v.x, 0.f); v.y = fmaxf(v.y, 0.f);
        v.z = fmaxf(v.z, 0.f); v.w = fmaxf(v.w, 0.f);
        *(__half2*)(Z + row * ZS + q * 4) = __floats2half2_rn(v.x, v.y);
        *(__half2*)(Z + row * ZS + q * 4 + 2) = __floats2half2_rn(v.z, v.w);
    }

#pragma unroll
    for (int pass = 0; pass < 2; pass++) {
        float acc[2][4][4];
#pragma unroll
        for (int mt = 0; mt < 2; mt++)
#pragma unroll
            for (int nt = 0; nt < 4; nt++)
#pragma unroll
                for (int j = 0; j < 4; j++) acc[mt][nt][j] = 0.f;

#pragma unroll
        for (int pc = 0; pc < 2; pc++) {
            if (pc == 0) CP_WAIT1(); else CP_WAIT0();
            __syncthreads();
            const __half* Wp = WB + pc * 9216;
#pragma unroll
            for (int ks = 0; ks < 4; ks++) {
                int kcol = pc * 64 + ks * 16 + tig * 2;
                u32 A[2][4];
#pragma unroll
                for (int mt = 0; mt < 2; mt++) {
                    int r = m_idx * 32 + mt * 16 + g;
                    A[mt][0] = *(const u32*)(Z + r * ZS + kcol);
                    A[mt][1] = *(const u32*)(Z + (r + 8) * ZS + kcol);
                    A[mt][2] = *(const u32*)(Z + r * ZS + kcol + 8);
                    A[mt][3] = *(const u32*)(Z + (r + 8) * ZS + kcol + 8);
                }
#pragma unroll
                for (int nt = 0; nt < 4; nt++) {
                    int n = n_idx * 32 + nt * 8 + g;
                    u32 B0 = *(const u32*)(Wp + n * 72 + ks * 16 + tig * 2);
                    u32 B1 = *(const u32*)(Wp + n * 72 + ks * 16 + tig * 2 + 8);
                    mma16(acc[0][nt], A[0], B0, B1);
                    mma16(acc[1][nt], A[1], B0, B1);
                }
            }
            __syncthreads();
        }

        if (pass == 0) {
#pragma unroll
            for (int mt = 0; mt < 2; mt++) {
#pragma unroll
                for (int nt = 0; nt < 4; nt++) {
                    int o0 = n_idx * 32 + nt * 8 + tig * 2;
                    int r0 = m_idx * 32 + mt * 16 + g;
                    float b0 = B1S[o0], b1 = B1S[o0 + 1];
                    *(__half2*)(Z + r0 * ZS + o0) = __floats2half2_rn(
                        fmaxf(acc[mt][nt][0] + b0, 0.f), fmaxf(acc[mt][nt][1] + b1, 0.f));
                    *(__half2*)(Z + (r0 + 8) * ZS + o0) = __floats2half2_rn(
                        fmaxf(acc[mt][nt][2] + b0, 0.f), fmaxf(acc[mt][nt][3] + b1, 0.f));
                }
            }
            __syncthreads();
#pragma unroll
            for (int pc = 0; pc < 2; pc++) {
                u32 d = smb + FWB_B + pc * 18432;
                const char* s = (const char*)(g_lin_h) + 36864 + pc * 18432;
#pragma unroll
                for (int j = 0; j < 5; j++) {
                    int e = tid + j * 256;
                    if (e < 1152) cpa16(d + e * 16, s + e * 16);
                }
                CP_COMMIT();
            }
        } else {
#pragma unroll
            for (int mt = 0; mt < 2; mt++) {
#pragma unroll
                for (int nt = 0; nt < 4; nt++) {
                    int o0 = n_idx * 32 + nt * 8 + tig * 2;
                    int r0 = m_idx * 32 + mt * 16 + g;
                    float b0 = B2S[o0], b1 = B2S[o0 + 1];
                    float2 v0, v1;
                    v0.x = acc[mt][nt][0] + b0;
                    v0.y = acc[mt][nt][1] + b1;
                    v1.x = acc[mt][nt][2] + b0;
                    v1.y = acc[mt][nt][3] + b1;
                    *(float2*)(out + ((size_t)(t0 + r0) * NB + b) * NC + o0) = v0;
                    *(float2*)(out + ((size_t)(t0 + r0 + 8) * NB + b) * NC + o0) = v1;
                }
            }
        }
    }
}

// ---------------- launch -----------------------------------------------------

extern "C" void kernel_launch(void* const* d_in, const int* in_sizes, int n_in,
                              void* d_out, int out_size) {
    const float* x      = (const float*)d_in[0];
    const float* pre_w  = (const float*)d_in[1];
    const float* pre_b  = (const float*)d_in[2];
    const float* conv_w = (const float*)d_in[3];
    const float* conv_b = (const float*)d_in[4];
    const float* post_w = (const float*)d_in[5];
    const float* post_b = (const float*)d_in[6];
    const float* lin1_w = (const float*)d_in[7];
    const float* lin1_b = (const float*)d_in[8];
    const float* lin2_w = (const float*)d_in[9];
    const float* lin2_b = (const float*)d_in[10];

    cudaFuncSetAttribute(layer_kernel, cudaFuncAttributeMaxDynamicSharedMemorySize, SMEM_LAYER);
    cudaFuncSetAttribute(final_kernel, cudaFuncAttributeMaxDynamicSharedMemorySize, SMEM_FINAL);

    tconv_kernel<<<10240, 256>>>(conv_w);
    tpost_kernel<<<2560, 256>>>(post_w);
    tlin_kernel<<<64, 256>>>(lin1_w, 0);
    tlin_kernel<<<64, 256>>>(lin2_w, 1);

    pre_kernel<<<NB * NT, 128>>>(x, pre_w, pre_b);

    for (int i = 0; i < NL; ++i) {
        int d = 1 << (i % 10);
        layer_kernel<<<128, 256, SMEM_LAYER>>>(i, d, i & 1, (i == 0) ? 1 : 0,
                                               conv_b, post_b);
    }

    final_kernel<<<512, 256, SMEM_FINAL>>>(lin1_b, lin2_b, (float*)d_out);
}

// round 14
// speedup vs baseline: 1.9113x; 1.9113x over previous
#include <cuda_runtime.h>
#include <cuda_fp16.h>

typedef unsigned int u32;

#define NB 4
#define NT 8192
#define NC 128
#define NL 40

// ---------------- persistent device scratch ----------------
__device__ float g_hA[NB * NT * NC];
__device__ float g_hB[NB * NT * NC];
__device__ __align__(128) __half g_h16A[NB * NT * NC];  // fp16 shadow of h (ping)
__device__ __align__(128) __half g_h16B[NB * NT * NC];  // fp16 shadow of h (pong)
__device__ float g_skip[NB * NT * NC];
// padded smem-image layouts (half):
// conv: [l][8 chunks][256 o'][40]  (32 k + 8 pad), o' interleaved filter/gate
__device__ __align__(128) __half g_wconv_h[NL * 8 * 256 * 40];
// post: [l][2 chunks][128 o][72]   (64 k + 8 pad)
__device__ __align__(128) __half g_wpost_h[NL * 2 * 128 * 72];
// lin:  [which][2 chunks][128 o][72]
__device__ __align__(128) __half g_lin_h[2 * 2 * 128 * 72];

// ---------------- helpers ----------------
__device__ __forceinline__ u32 smem_u32(const void* p) {
    u32 a;
    asm("{ .reg .u64 t; cvta.to.shared.u64 t, %1; cvt.u32.u64 %0, t; }" : "=r"(a) : "l"(p));
    return a;
}
__device__ __forceinline__ void cpa16(u32 dst, const void* src) {
    asm volatile("cp.async.cg.shared.global [%0], [%1], 16;" :: "r"(dst), "l"(src));
}
__device__ __forceinline__ void cpa16z(u32 dst, const void* src, u32 n) {
    asm volatile("cp.async.cg.shared.global [%0], [%1], 16, %2;" :: "r"(dst), "l"(src), "r"(n));
}
#define CP_COMMIT() asm volatile("cp.async.commit_group;" ::: "memory")
#define CP_WAIT0() asm volatile("cp.async.wait_group 0;" ::: "memory")
#define CP_WAIT1() asm volatile("cp.async.wait_group 1;" ::: "memory")

__device__ __forceinline__ void mma16(float c[4], const u32 a[4], u32 b0, u32 b1) {
    asm volatile(
        "mma.sync.aligned.m16n8k16.row.col.f32.f16.f16.f32 "
        "{%0,%1,%2,%3}, {%4,%5,%6,%7}, {%8,%9}, {%0,%1,%2,%3};"
        : "+f"(c[0]), "+f"(c[1]), "+f"(c[2]), "+f"(c[3])
        : "r"(a[0]), "r"(a[1]), "r"(a[2]), "r"(a[3]), "r"(b0), "r"(b1));
}
__device__ __forceinline__ void ldm4(u32 r[4], u32 addr) {
    asm volatile("ldmatrix.sync.aligned.m8n8.x4.shared.b16 {%0,%1,%2,%3}, [%4];"
        : "=r"(r[0]), "=r"(r[1]), "=r"(r[2]), "=r"(r[3]) : "r"(addr));
}

// ---------------- merged weight transpose (ONE launch) ----------------------

#define N_CONV_EL (NL * 256 * 128 * 2)
#define N_POST_EL (NL * 128 * 128)
#define N_LIN_EL  (2 * 128 * 128)
#define N_TRANS_TH (N_CONV_EL + N_POST_EL + N_LIN_EL)

__global__ void trans_kernel(const float* __restrict__ cw, const float* __restrict__ pw,
                             const float* __restrict__ l1, const float* __restrict__ l2) {
    int idx = blockIdx.x * blockDim.x + threadIdx.x;
    if (idx < N_CONV_EL) {
        // cw: [L][256 og][128 c][2 tap]
        int tap = idx & 1;
        int c = (idx >> 1) & 127;
        int og = (idx >> 8) & 255;
        int l = idx >> 16;
        int kg = tap * 128 + c;                    // K: 0-127 = h[t-d], 128-255 = h[t]
        int kc = kg >> 5, ki = kg & 31;
        int op = (og < 128) ? (og * 2) : ((og - 128) * 2 + 1);
        g_wconv_h[((l * 8 + kc) * 256 + op) * 40 + ki] = __float2half_rn(cw[idx]);
    } else if (idx < N_CONV_EL + N_POST_EL) {
        int j = idx - N_CONV_EL;                   // pw: [L][128 o][128 c]
        int c = j & 127;
        int o = (j >> 7) & 127;
        int l = j >> 14;
        g_wpost_h[((l * 2 + (c >> 6)) * 128 + o) * 72 + (c & 63)] = __float2half_rn(pw[j]);
    } else {
        int j = idx - (N_CONV_EL + N_POST_EL);     // lin: [128 o][128 i]
        int which = j >> 14;
        int k = j & 16383;
        int i = k & 127;
        int o = k >> 7;
        const float* w = which ? l2 : l1;
        g_lin_h[((which * 2 + (i >> 6)) * 128 + o) * 72 + (i & 63)] = __float2half_rn(w[k]);
    }
}

// ---------------- pre-net ----------------

__global__ void pre_kernel(const float* __restrict__ x,
                           const float* __restrict__ w,
                           const float* __restrict__ b) {
    int bt = blockIdx.x;
    int bb = bt >> 13;
    int t = bt & 8191;
    int c = threadIdx.x;
    const float* xb = x + bb * NT;
    float x0 = (t >= 2) ? xb[t - 2] : 0.f;
    float x1 = (t >= 1) ? xb[t - 1] : 0.f;
    float x2 = xb[t];
    float v = w[c * 3 + 0] * x0 + w[c * 3 + 1] * x1 + w[c * 3 + 2] * x2 + b[c];
    g_hA[bt * NC + c] = v;
    g_h16A[bt * NC + c] = __float2half_rn(v);
}

// ---------------- fused WaveNet block (fp16 mma, 3-stage cp.async, LDSM) ----
// smem bytes: X [64 rows][264 halves] @0 (33792); WB @33792 (3 conv bufs of
//             10240 halves = 61440B; post reuses buf0/buf2); CBS @95232 (1024);
//             PBS @96256 (512). total 96768.

#define WB_B 33792
#define CB_B 95232
#define PB_B 96256
#define SMEM_LAYER 96768
#define XS 264

__global__ void __launch_bounds__(256, 2)
layer_kernel(int l, int dil, int flip, int first,
             const float* __restrict__ conv_b,
             const float* __restrict__ post_b) {
    const float* __restrict__ h_in = flip ? g_hB : g_hA;
    float* __restrict__ h_out = flip ? g_hA : g_hB;
    const __half* __restrict__ h16_in = flip ? g_h16B : g_h16A;
    __half* __restrict__ h16_out = flip ? g_h16A : g_h16B;

    extern __shared__ char smx[];
    __half* X = (__half*)smx;
    float* CBS = (float*)(smx + CB_B);
    float* PBS = (float*)(smx + PB_B);
    u32 smb = smem_u32(smx);

    int tid = threadIdx.x;
    int lane = tid & 31, wid = tid >> 5;
    int g = lane >> 2, tig = lane & 3;
    int m_idx = wid >> 2, n_idx = wid & 3;

    // ldmatrix per-lane address components
    u32 arow = (u32)(lane & 15);              // A fragment row within 16-row block
    u32 a_kx = (u32)((lane >> 4) << 4);       // +16B for k+8 halves
    u32 brow = (u32)((lane & 7) | ((lane & 16) >> 1));  // B row within 16-n block
    u32 b_kx = (u32)((lane & 8) << 1);        // +16B for k+8 halves
    u32 xab = smb + (m_idx * 32 + arow) * 528 + a_kx;          // A base (mt=0)
    u32 bcb = (u32)(n_idx * 64 + brow) * 80 + b_kx;            // conv B lane off
    u32 pcb = (u32)(n_idx * 32 + brow) * 144 + b_kx;           // post B lane off

    int b = blockIdx.x >> 7;
    int t0 = (blockIdx.x & 127) << 6;

    const char* wcl = (const char*)(g_wconv_h) + (size_t)l * 163840;
    const char* wpl = (const char*)(g_wpost_h) + (size_t)l * 36864;

    // ---- async X staging: [64 rows][256 k] fp16 from h16 shadow ----
    {
        const __half* h16b = h16_in + (size_t)b * NT * NC;
#pragma unroll
        for (int j = 0; j < 8; j++) {
            int e = tid + j * 256;
            int row = e >> 5, s = e & 31;
            u32 dst = smb + row * 528 + s * 16;
            if (s < 16) {
                int tp = t0 + row - dil;
                const __half* src = h16b + (size_t)(tp < 0 ? 0 : tp) * NC + s * 8;
                cpa16z(dst, src, (tp >= 0) ? 16u : 0u);
            } else {
                const __half* src = h16b + (size_t)(t0 + row) * NC + (s - 16) * 8;
                cpa16(dst, src);
            }
        }
        u32 d = smb + WB_B;
#pragma unroll
        for (int j = 0; j < 5; j++)
            cpa16(d + (tid + j * 256) * 16, wcl + (tid + j * 256) * 16);
        CP_COMMIT();  // G0: X + conv chunk 0
        d = smb + WB_B + 20480;
#pragma unroll
        for (int j = 0; j < 5; j++)
            cpa16(d + (tid + j * 256) * 16, wcl + 20480 + (tid + j * 256) * 16);
        CP_COMMIT();  // G1: conv chunk 1
    }

    CBS[tid] = conv_b[l * 256 + ((tid & 1) ? 128 + (tid >> 1) : (tid >> 1))];
    if (tid < 128) PBS[tid] = post_b[l * 128 + tid];

    float acc[2][8][4];
#pragma unroll
    for (int mt = 0; mt < 2; mt++)
#pragma unroll
        for (int nt = 0; nt < 8; nt++)
#pragma unroll
            for (int j = 0; j < 4; j++) acc[mt][nt][j] = 0.f;

    // ---- conv GEMM: C[64t, 256o'] = X[64,256] * W[256,256], 8 k-chunks ----
    for (int kc = 0; kc < 8; kc++) {
        if (kc < 7) CP_WAIT1(); else CP_WAIT0();
        __syncthreads();
        if (kc < 6) {
            u32 d = smb + WB_B + ((kc + 2) % 3) * 20480;
            const char* s = wcl + (kc + 2) * 20480;
#pragma unroll
            for (int j = 0; j < 5; j++)
                cpa16(d + (tid + j * 256) * 16, s + (tid + j * 256) * 16);
            CP_COMMIT();
        } else if (kc == 7) {
#pragma unroll
            for (int pc = 0; pc < 2; pc++) {
                u32 d = smb + WB_B + (pc ? 2 : 0) * 20480;
                const char* s = wpl + pc * 18432;
#pragma unroll
                for (int j = 0; j < 5; j++) {
                    int e = tid + j * 256;
                    if (e < 1152) cpa16(d + e * 16, s + e * 16);
                }
                CP_COMMIT();  // G8, G9
            }
        }
        u32 wb = smb + WB_B + (kc % 3) * 20480;
#pragma unroll
        for (int ks = 0; ks < 2; ks++) {
            u32 A[2][4];
            ldm4(A[0], xab + kc * 64 + ks * 32);
            ldm4(A[1], xab + 8448 + kc * 64 + ks * 32);
#pragma unroll
            for (int ntp = 0; ntp < 4; ntp++) {
                u32 B[4];
                ldm4(B, wb + bcb + ntp * 1280 + ks * 32);
                mma16(acc[0][ntp * 2],     A[0], B[0], B[1]);
                mma16(acc[1][ntp * 2],     A[1], B[0], B[1]);
                mma16(acc[0][ntp * 2 + 1], A[0], B[2], B[3]);
                mma16(acc[1][ntp * 2 + 1], A[1], B[2], B[3]);
            }
        }
    }

    // ---- GLU epilogue: skip = a*sigmoid(gate); skip_sum RMW; skip -> X[:,0:128]
    int r0g = m_idx * 32 + g;
    float* gsk = g_skip + ((size_t)b * NT + t0) * NC;
#pragma unroll
    for (int mt = 0; mt < 2; mt++) {
#pragma unroll
        for (int nt = 0; nt < 8; nt++) {
            int o0 = n_idx * 64 + nt * 8 + tig * 2;
            int ch = o0 >> 1;
            float cb0 = CBS[o0], cb1 = CBS[o0 + 1];
            int rr = r0g + mt * 16;
            float a0 = acc[mt][nt][0] + cb0, g0 = acc[mt][nt][1] + cb1;
            float a1 = acc[mt][nt][2] + cb0, g1 = acc[mt][nt][3] + cb1;
            float s0 = a0 / (1.f + __expf(-g0));
            float s1 = a1 / (1.f + __expf(-g1));
            if (first) {
                gsk[rr * NC + ch] = s0;
                gsk[(rr + 8) * NC + ch] = s1;
            } else {
                gsk[rr * NC + ch] += s0;
                gsk[(rr + 8) * NC + ch] += s1;
            }
            X[rr * XS + ch] = __float2half_rn(s0);
            X[(rr + 8) * XS + ch] = __float2half_rn(s1);
        }
    }

    // ---- post GEMM: D[64t,128o] = skip[64,128] * Wp[128,128], 2 k-chunks ----
    float accp[2][4][4];
#pragma unroll
    for (int mt = 0; mt < 2; mt++)
#pragma unroll
        for (int nt = 0; nt < 4; nt++)
#pragma unroll
            for (int j = 0; j < 4; j++) accp[mt][nt][j] = 0.f;

#pragma unroll
    for (int pc = 0; pc < 2; pc++) {
        if (pc == 0) CP_WAIT1(); else CP_WAIT0();
        __syncthreads();  // post-W arrival + GLU skip-tile store visibility
        u32 wb = smb + WB_B + (pc ? 2 : 0) * 20480;
#pragma unroll
        for (int ks = 0; ks < 4; ks++) {
            u32 A[2][4];
            ldm4(A[0], xab + pc * 128 + ks * 32);
            ldm4(A[1], xab + 8448 + pc * 128 + ks * 32);
#pragma unroll
            for (int ntp = 0; ntp < 2; ntp++) {
                u32 B[4];
                ldm4(B, wb + pcb + ntp * 2304 + ks * 32);
                mma16(accp[0][ntp * 2],     A[0], B[0], B[1]);
                mma16(accp[1][ntp * 2],     A[1], B[0], B[1]);
                mma16(accp[0][ntp * 2 + 1], A[0], B[2], B[3]);
                mma16(accp[1][ntp * 2 + 1], A[1], B[2], B[3]);
            }
        }
    }

    // ---- residual epilogue (fp32 h path) + fp16 shadow write ----
    const float* hres = h_in + ((size_t)b * NT + t0) * NC;
    float* hdst = h_out + ((size_t)b * NT + t0) * NC;
    __half* hdst16 = h16_out + ((size_t)b * NT + t0) * NC;
#pragma unroll
    for (int mt = 0; mt < 2; mt++) {
#pragma unroll
        for (int nt = 0; nt < 4; nt++) {
            int o0 = n_idx * 32 + nt * 8 + tig * 2;
            int rr = r0g + mt * 16;
            float pb0 = PBS[o0], pb1 = PBS[o0 + 1];
            float2 h0 = *(const float2*)(hres + rr * NC + o0);
            float2 h1 = *(const float2*)(hres + (rr + 8) * NC + o0);
            float2 v0, v1;
            v0.x = h0.x + accp[mt][nt][0] + pb0;
            v0.y = h0.y + accp[mt][nt][1] + pb1;
            v1.x = h1.x + accp[mt][nt][2] + pb0;
            v1.y = h1.y + accp[mt][nt][3] + pb1;
            *(float2*)(hdst + rr * NC + o0) = v0;
            *(float2*)(hdst + (rr + 8) * NC + o0) = v1;
            *(__half2*)(hdst16 + rr * NC + o0) = __floats2half2_rn(v0.x, v0.y);
            *(__half2*)(hdst16 + (rr + 8) * NC + o0) = __floats2half2_rn(v1.x, v1.y);
        }
    }
}

// ---------------- final: relu -> lin1 -> relu -> lin2 (fp16 mma) ------------

#define FWB_B 17408
#define FB1_B 54272
#define FB2_B 54784
#define SMEM_FINAL 55296
#define ZS 136

__global__ void __launch_bounds__(256, 2)
final_kernel(const float* __restrict__ lin1_b,
             const float* __restrict__ lin2_b,
             float* __restrict__ out) {
    extern __shared__ char smx[];
    __half* Z = (__half*)smx;
    __half* WB = (__half*)(smx + FWB_B);
    float* B1S = (float*)(smx + FB1_B);
    float* B2S = (float*)(smx + FB2_B);
    u32 smb = smem_u32(smx);

    int tid = threadIdx.x;
    int lane = tid & 31, wid = tid >> 5;
    int g = lane >> 2, tig = lane & 3;
    int m_idx = wid >> 2, n_idx = wid & 3;

    int b = blockIdx.x >> 7;
    int t0 = (blockIdx.x & 127) << 6;

#pragma unroll
    for (int pc = 0; pc < 2; pc++) {
        u32 d = smb + FWB_B + pc * 18432;
        const char* s = (const char*)(g_lin_h) + pc * 18432;
#pragma unroll
        for (int j = 0; j < 5; j++) {
            int e = tid + j * 256;
            if (e < 1152) cpa16(d + e * 16, s + e * 16);
        }
        CP_COMMIT();
    }

    if (tid < 128) {
        B1S[tid] = lin1_b[tid];
        B2S[tid] = lin2_b[tid];
    }

    const float* zb = g_skip + ((size_t)b * NT + t0) * NC;
#pragma unroll
    for (int i = 0; i < 8; i++) {
        int e = tid + i * 256;
        int row = e >> 5, q = e & 31;
        float4 v = *(const float4*)(zb + (size_t)row * NC + q * 4);
        v.x = fmaxf(v.x, 0.f); v.y = fmaxf(v.y, 0.f);
        v.z = fmaxf(v.z, 0.f); v.w = fmaxf(v.w, 0.f);
        *(__half2*)(Z + row * ZS + q * 4) = __floats2half2_rn(v.x, v.y);
        *(__half2*)(Z + row * ZS + q * 4 + 2) = __floats2half2_rn(v.z, v.w);
    }

#pragma unroll
    for (int pass = 0; pass < 2; pass++) {
        float acc[2][4][4];
#pragma unroll
        for (int mt = 0; mt < 2; mt++)
#pragma unroll
            for (int nt = 0; nt < 4; nt++)
#pragma unroll
                for (int j = 0; j < 4; j++) acc[mt][nt][j] = 0.f;

#pragma unroll
        for (int pc = 0; pc < 2; pc++) {
            if (pc == 0) CP_WAIT1(); else CP_WAIT0();
            __syncthreads();
            const __half* Wp = WB + pc * 9216;
#pragma unroll
            for (int ks = 0; ks < 4; ks++) {
                int kcol = pc * 64 + ks * 16 + tig * 2;
                u32 A[2][4];
#pragma unroll
                for (int mt = 0; mt < 2; mt++) {
                    int r = m_idx * 32 + mt * 16 + g;
                    A[mt][0] = *(const u32*)(Z + r * ZS + kcol);
                    A[mt][1] = *(const u32*)(Z + (r + 8) * ZS + kcol);
                    A[mt][2] = *(const u32*)(Z + r * ZS + kcol + 8);
                    A[mt][3] = *(const u32*)(Z + (r + 8) * ZS + kcol + 8);
                }
#pragma unroll
                for (int nt = 0; nt < 4; nt++) {
                    int n = n_idx * 32 + nt * 8 + g;
                    u32 B0 = *(const u32*)(Wp + n * 72 + ks * 16 + tig * 2);
                    u32 B1 = *(const u32*)(Wp + n * 72 + ks * 16 + tig * 2 + 8);
                    mma16(acc[0][nt], A[0], B0, B1);
                    mma16(acc[1][nt], A[1], B0, B1);
                }
            }
            __syncthreads();
        }

        if (pass == 0) {
#pragma unroll
            for (int mt = 0; mt < 2; mt++) {
#pragma unroll
                for (int nt = 0; nt < 4; nt++) {
                    int o0 = n_idx * 32 + nt * 8 + tig * 2;
                    int r0 = m_idx * 32 + mt * 16 + g;
                    float b0 = B1S[o0], b1 = B1S[o0 + 1];
                    *(__half2*)(Z + r0 * ZS + o0) = __floats2half2_rn(
                        fmaxf(acc[mt][nt][0] + b0, 0.f), fmaxf(acc[mt][nt][1] + b1, 0.f));
                    *(__half2*)(Z + (r0 + 8) * ZS + o0) = __floats2half2_rn(
                        fmaxf(acc[mt][nt][2] + b0, 0.f), fmaxf(acc[mt][nt][3] + b1, 0.f));
                }
            }
            __syncthreads();
#pragma unroll
            for (int pc = 0; pc < 2; pc++) {
                u32 d = smb + FWB_B + pc * 18432;
                const char* s = (const char*)(g_lin_h) + 36864 + pc * 18432;
#pragma unroll
                for (int j = 0; j < 5; j++) {
                    int e = tid + j * 256;
                    if (e < 1152) cpa16(d + e * 16, s + e * 16);
                }
                CP_COMMIT();
            }
        } else {
#pragma unroll
            for (int mt = 0; mt < 2; mt++) {
#pragma unroll
                for (int nt = 0; nt < 4; nt++) {
                    int o0 = n_idx * 32 + nt * 8 + tig * 2;
                    int r0 = m_idx * 32 + mt * 16 + g;
                    float b0 = B2S[o0], b1 = B2S[o0 + 1];
                    float2 v0, v1;
                    v0.x = acc[mt][nt][0] + b0;
                    v0.y = acc[mt][nt][1] + b1;
                    v1.x = acc[mt][nt][2] + b0;
                    v1.y = acc[mt][nt][3] + b1;
                    *(float2*)(out + ((size_t)(t0 + r0) * NB + b) * NC + o0) = v0;
                    *(float2*)(out + ((size_t)(t0 + r0 + 8) * NB + b) * NC + o0) = v1;
                }
            }
        }
    }
}

// ---------------- launch -----------------------------------------------------

extern "C" void kernel_launch(void* const* d_in, const int* in_sizes, int n_in,
                              void* d_out, int out_size) {
    const float* x      = (const float*)d_in[0];
    const float* pre_w  = (const float*)d_in[1];
    const float* pre_b  = (const float*)d_in[2];
    const float* conv_w = (const float*)d_in[3];
    const float* conv_b = (const float*)d_in[4];
    const float* post_w = (const float*)d_in[5];
    const float* post_b = (const float*)d_in[6];
    const float* lin1_w = (const float*)d_in[7];
    const float* lin1_b = (const float*)d_in[8];
    const float* lin2_w = (const float*)d_in[9];
    const float* lin2_b = (const float*)d_in[10];

    cudaFuncSetAttribute(layer_kernel, cudaFuncAttributeMaxDynamicSharedMemorySize, SMEM_LAYER);
    cudaFuncSetAttribute(final_kernel, cudaFuncAttributeMaxDynamicSharedMemorySize, SMEM_FINAL);

    // ONE transpose launch (also puts layer_kernel into ncu's -s 5 window)
    trans_kernel<<<N_TRANS_TH / 256, 256>>>(conv_w, post_w, lin1_w, lin2_w);

    pre_kernel<<<NB * NT, 128>>>(x, pre_w, pre_b);

    for (int i = 0; i < NL; ++i) {
        int d = 1 << (i % 10);
        layer_kernel<<<512, 256, SMEM_LAYER>>>(i, d, i & 1, (i == 0) ? 1 : 0,
                                               conv_b, post_b);
    }

    final_kernel<<<512, 256, SMEM_FINAL>>>(lin1_b, lin2_b, (float*)d_out);
}